// round 12
// baseline (speedup 1.0000x reference)
#include <cuda_runtime.h>

// DynamicKVCache update: out = [concat(cache_k, key, dim=1), concat(cache_v, value, dim=1)]
// Shapes: cache [8, 4096, 32, 128] f32, new [8, 1, 32, 128] f32.
//
// FINAL — converged at the B300 HBM mixed-stream roofline (R2-R11).
// Probe matrix: MLP_p1 {1,4,8}, occupancy {60-85%}, chunk {16,32}KB,
// request width {16B,32B}, R/W ordering {burst, interleaved}. Kernel time
// invariant at 298.6-301.6us across 6 runs of this config; session-best
// 298.6us = 7.01 TB/s = 88.4% DRAM-active. Irreducible traffic = 2.148 GB;
// analytical floor at the 50/50 R/W-stream ceiling (~88% of 8 TB/s spec)
// is ~299us — we measure exactly that. Residual vs spec is DRAM bus
// turnaround, not kernel-addressable (LDG/TMA/LTS share one chip cap).
//
// Config: 256 threads x 8 float4 (32KB chunk), 8 back-to-back LDG.128 then
// 8 STG.128 per thread, evict-first (.cs) hints. Cache region = 2048 exact
// chunks/batch; appended key/value slot = one half-chunk tail block per
// batch (uniform per-block branch). Grid = (2049, 8 batches, 2 tensors).

static constexpr long long CACHE_F4  = 4096LL * 4096 / 4;    // 4,194,304
static constexpr long long NEW_F4    = 4096LL / 4;           // 1,024
static constexpr long long BATCH_F4  = CACHE_F4 + NEW_F4;    // 4,195,328
static constexpr long long TENSOR_F4 = 8LL * BATCH_F4;
static constexpr int THREADS   = 256;
static constexpr int PER_TH    = 8;                          // float4 per thread (full chunk)
static constexpr int CHUNK_F4  = THREADS * PER_TH;           // 2048
static constexpr int CACHE_CHUNKS = (int)(CACHE_F4 / CHUNK_F4); // 2048, exact
static constexpr int BLOCKS_X  = CACHE_CHUNKS + 1;           // +1 tail (new slot, 1024 f4)

__global__ __launch_bounds__(THREADS)
void kvcache_concat_kernel(const float4* __restrict__ cache_k,
                           const float4* __restrict__ cache_v,
                           const float4* __restrict__ key,
                           const float4* __restrict__ value,
                           float4* __restrict__ out)
{
    const int chunk = blockIdx.x;    // [0, 2049)
    const int b     = blockIdx.y;    // batch
    const int t     = blockIdx.z;    // 0 = k, 1 = v

    const long long out_base = (long long)t * TENSOR_F4
                             + (long long)b * BATCH_F4
                             + (long long)chunk * CHUNK_F4;
    const int tid = threadIdx.x;

    const float4* __restrict__ cache = t ? cache_v : cache_k;
    const float4* __restrict__ nw    = t ? value   : key;

    if (chunk < CACHE_CHUNKS) {
        // Full 32KB chunk: 8 independent coalesced LDG.128, then 8 STG.128.
        const float4* __restrict__ src =
            cache + (long long)b * CACHE_F4 + (long long)chunk * CHUNK_F4;
        float4 v[PER_TH];
#pragma unroll
        for (int j = 0; j < PER_TH; j++)
            v[j] = __ldcs(src + tid + j * THREADS);
#pragma unroll
        for (int j = 0; j < PER_TH; j++)
            __stcs(out + out_base + tid + j * THREADS, v[j]);
    } else {
        // Appended slot: 1024 float4 (half chunk), uniform per-block path.
        const float4* __restrict__ src = nw + (long long)b * NEW_F4;
        float4 v[4];
#pragma unroll
        for (int j = 0; j < 4; j++)
            v[j] = __ldcs(src + tid + j * THREADS);
#pragma unroll
        for (int j = 0; j < 4; j++)
            __stcs(out + out_base + tid + j * THREADS, v[j]);
    }
}

extern "C" void kernel_launch(void* const* d_in, const int* in_sizes, int n_in,
                              void* d_out, int out_size)
{
    const float4* cache_k = (const float4*)d_in[0];
    const float4* cache_v = (const float4*)d_in[1];
    const float4* key     = (const float4*)d_in[2];
    const float4* value   = (const float4*)d_in[3];
    float4* out = (float4*)d_out;

    dim3 grid(BLOCKS_X, 8, 2);
    kvcache_concat_kernel<<<grid, THREADS>>>(cache_k, cache_v, key, value, out);
}

// round 13
// speedup vs baseline: 1.0032x; 1.0032x over previous
#include <cuda_runtime.h>

// DynamicKVCache update: out = [concat(cache_k, key, dim=1), concat(cache_v, value, dim=1)]
// Shapes: cache [8, 4096, 32, 128] f32, new [8, 1, 32, 128] f32.
//
// Converged at the B300 HBM mixed-stream roofline (R2-R12: kernel time
// 298.6-301.6us, DRAM-active 87.5-88.4%, invariant across MLP/occ/chunk/
// width/ordering probes; analytical floor ~299us for 2.148 GB at the
// ~88% 50/50-stream ceiling). This round completes the probe matrix with
// the one unsampled cell: 512 threads/block x 4 float4 (same 32KB chunk,
// coarser CTA scheduling quanta). Model prediction: neutral.

static constexpr long long CACHE_F4  = 4096LL * 4096 / 4;    // 4,194,304
static constexpr long long NEW_F4    = 4096LL / 4;           // 1,024
static constexpr long long BATCH_F4  = CACHE_F4 + NEW_F4;    // 4,195,328
static constexpr long long TENSOR_F4 = 8LL * BATCH_F4;
static constexpr int THREADS   = 512;
static constexpr int PER_TH    = 4;                          // float4 per thread (full chunk)
static constexpr int CHUNK_F4  = THREADS * PER_TH;           // 2048
static constexpr int CACHE_CHUNKS = (int)(CACHE_F4 / CHUNK_F4); // 2048, exact
static constexpr int BLOCKS_X  = CACHE_CHUNKS + 1;           // +1 tail (new slot, 1024 f4)

__global__ __launch_bounds__(THREADS)
void kvcache_concat_kernel(const float4* __restrict__ cache_k,
                           const float4* __restrict__ cache_v,
                           const float4* __restrict__ key,
                           const float4* __restrict__ value,
                           float4* __restrict__ out)
{
    const int chunk = blockIdx.x;    // [0, 2049)
    const int b     = blockIdx.y;    // batch
    const int t     = blockIdx.z;    // 0 = k, 1 = v

    const long long out_base = (long long)t * TENSOR_F4
                             + (long long)b * BATCH_F4
                             + (long long)chunk * CHUNK_F4;
    const int tid = threadIdx.x;

    const float4* __restrict__ cache = t ? cache_v : cache_k;
    const float4* __restrict__ nw    = t ? value   : key;

    if (chunk < CACHE_CHUNKS) {
        // Full 32KB chunk: 4 independent coalesced LDG.128, then 4 STG.128.
        const float4* __restrict__ src =
            cache + (long long)b * CACHE_F4 + (long long)chunk * CHUNK_F4;
        float4 v[PER_TH];
#pragma unroll
        for (int j = 0; j < PER_TH; j++)
            v[j] = __ldcs(src + tid + j * THREADS);
#pragma unroll
        for (int j = 0; j < PER_TH; j++)
            __stcs(out + out_base + tid + j * THREADS, v[j]);
    } else {
        // Appended slot: 1024 float4 (half chunk), uniform per-block path.
        const float4* __restrict__ src = nw + (long long)b * NEW_F4;
        float4 v0 = __ldcs(src + tid);
        float4 v1 = __ldcs(src + tid + THREADS);
        __stcs(out + out_base + tid,           v0);
        __stcs(out + out_base + tid + THREADS, v1);
    }
}

extern "C" void kernel_launch(void* const* d_in, const int* in_sizes, int n_in,
                              void* d_out, int out_size)
{
    const float4* cache_k = (const float4*)d_in[0];
    const float4* cache_v = (const float4*)d_in[1];
    const float4* key     = (const float4*)d_in[2];
    const float4* value   = (const float4*)d_in[3];
    float4* out = (float4*)d_out;

    dim3 grid(BLOCKS_X, 8, 2);
    kvcache_concat_kernel<<<grid, THREADS>>>(cache_k, cache_v, key, value, out);
}